// round 7
// baseline (speedup 1.0000x reference)
#include <cuda_runtime.h>
#include <cstdint>

// ---------------- problem constants ----------------
#define BB    16
#define CIN   512
#define COUT  512
#define SDIM  512
#define HI    32
#define WI    32
#define HO    64
#define WO    64
#define PADW  66
#define KTOT  (9 * CIN)          // 4608

#define LIN_SCALE  0.04419417382415922f
#define CONV_SCALE 0.014731391274719742f
#define ACT_GAIN   1.4142135623730951f
#define NEG_SLOPE  0.2f
#define EPS_DEMOD  1e-8f

// ---------------- device scratch ----------------
__device__ float g_s[BB * CIN];
__device__ float g_demod[BB * COUT];
__device__ float g_wt[(size_t)COUT * KTOT];             // tf32, k-pair-permuted
__device__ float g_wsq[COUT * CIN];
__device__ float g_xt[(size_t)BB * HI * WI * CIN];      // channel-last input
__device__ float g_xm[(size_t)BB * PADW * PADW * CIN];  // tf32, k-pair-permuted

// k-pair permutation within each ci-octet: 0,4,1,5,2,6,3,7
// (so fragment operands k and k+4 are adjacent in memory)
__device__ __forceinline__ int kperm(int i) {
    return (i & ~7) | (2 * (i & 3) + ((i >> 2) & 1));
}

// ---------------- helpers ----------------
__device__ __forceinline__ float to_tf32(float x) {
    uint32_t r;
    asm("cvt.rna.tf32.f32 %0, %1;" : "=r"(r) : "f"(x));
    return __uint_as_float(r);
}
__device__ __forceinline__ uint32_t smem_u32(const void* p) {
    uint32_t a;
    asm("{ .reg .u64 t; cvta.to.shared.u64 t, %1; cvt.u32.u64 %0, t; }"
        : "=r"(a) : "l"(p));
    return a;
}
__device__ __forceinline__ void cpasync16(uint32_t dst, const void* src) {
    asm volatile("cp.async.cg.shared.global [%0], [%1], 16;"
                 :: "r"(dst), "l"(src) : "memory");
}
__device__ __forceinline__ void cp_commit() {
    asm volatile("cp.async.commit_group;" ::: "memory");
}
template<int N> __device__ __forceinline__ void cp_wait() {
    asm volatile("cp.async.wait_group %0;" :: "n"(N) : "memory");
}
__device__ __forceinline__ void mma_tf32(float* c, const uint32_t* a,
                                         uint32_t b0, uint32_t b1) {
    asm volatile(
        "mma.sync.aligned.m16n8k8.row.col.f32.tf32.tf32.f32 "
        "{%0,%1,%2,%3}, {%4,%5,%6,%7}, {%8,%9}, {%0,%1,%2,%3};"
        : "+f"(c[0]), "+f"(c[1]), "+f"(c[2]), "+f"(c[3])
        : "r"(a[0]), "r"(a[1]), "r"(a[2]), "r"(a[3]), "r"(b0), "r"(b1));
}

// ---------------- kernel 1: style ----------------
__global__ void style_kernel(const float* __restrict__ w,
                             const float* __restrict__ lin_w,
                             const float* __restrict__ lin_b)
{
    const int b = blockIdx.x, i = threadIdx.x;
    __shared__ float ws[SDIM];
    ws[i] = w[b * SDIM + i];
    __syncthreads();
    const float* lw = lin_w + (size_t)i * SDIM;
    float acc = 0.f;
#pragma unroll 8
    for (int j = 0; j < SDIM; ++j) acc = fmaf(ws[j], lw[j], acc);
    g_s[b * CIN + i] = acc * LIN_SCALE + lin_b[i];
}

// ---------------- kernel 2: weight K-major (tf32, permuted) + sumsq --------
__global__ void wprep_kernel(const float* __restrict__ conv_w)
{
    const int o = blockIdx.x, i = threadIdx.x;
    const float* wp = conv_w + ((size_t)o * CIN + i) * 9;
    const int ip = kperm(i);
    float q = 0.f;
#pragma unroll
    for (int kk = 0; kk < 9; ++kk) {
        const float v = wp[kk] * CONV_SCALE;
        g_wt[(size_t)o * KTOT + kk * CIN + ip] = to_tf32(v);
        q = fmaf(v, v, q);   // exact fp32 for demod
    }
    g_wsq[o * CIN + i] = q;
}

// ---------------- kernel 3: demod ----------------
__global__ void demod_kernel()
{
    const int b = blockIdx.x, o = threadIdx.x;
    __shared__ float s2[CIN];
    const float sv = g_s[b * CIN + o];
    s2[o] = sv * sv;
    __syncthreads();
    const float* wq = g_wsq + (size_t)o * CIN;
    float acc = 0.f;
#pragma unroll 8
    for (int i = 0; i < CIN; ++i) acc = fmaf(wq[i], s2[i], acc);
    g_demod[b * COUT + o] = rsqrtf(acc + EPS_DEMOD);
}

// ---------------- kernel 4a: transpose x to channel-last ----------------
__global__ void transpose_kernel(const float* __restrict__ x)
{
    __shared__ float tile[32][33];
    const int b = blockIdx.z, p0 = blockIdx.x * 32, c0 = blockIdx.y * 32;
    const int tx = threadIdx.x, ty = threadIdx.y;     // (32, 8)
    for (int i = ty; i < 32; i += 8)
        tile[i][tx] = x[((size_t)(b * CIN) + c0 + i) * (HI * WI) + p0 + tx];
    __syncthreads();
    for (int i = ty; i < 32; i += 8)
        g_xt[((size_t)(b * HI * WI) + p0 + i) * CIN + c0 + tx] = tile[tx][i];
}

// ------ kernel 4b: upsample*style, channel-last, zero halo, tf32, permuted -
__global__ void upmod_cl_kernel()
{
    const int r = blockIdx.x;         // 0..65
    const int b = blockIdx.y;
    const int ci = threadIdx.x;       // 512
    const int cip = kperm(ci);
    float* dst = g_xm + ((size_t)(b * PADW + r) * PADW) * CIN + cip;
    if (r == 0 || r == PADW - 1) {
        for (int c = 0; c < PADW; ++c) dst[(size_t)c * CIN] = 0.f;
        return;
    }
    const int oy = r - 1, my = oy >> 1;
    int iy0, iy1; float wy0;
    if (oy & 1) { iy0 = my; iy1 = min(my + 1, HI - 1); wy0 = 0.75f; }
    else        { iy0 = max(my - 1, 0); iy1 = my;      wy0 = 0.25f; }
    const float wy1 = 1.f - wy0;
    const float s = g_s[b * CIN + ci];
    const float* xb = g_xt + (size_t)b * HI * WI * CIN + ci;
    dst[0] = 0.f;
    dst[(size_t)(PADW - 1) * CIN] = 0.f;
    for (int c = 1; c < PADW - 1; ++c) {
        const int ox = c - 1, mx = ox >> 1;
        int ix0, ix1; float wx0;
        if (ox & 1) { ix0 = mx; ix1 = min(mx + 1, WI - 1); wx0 = 0.75f; }
        else        { ix0 = max(mx - 1, 0); ix1 = mx;      wx0 = 0.25f; }
        const float wx1 = 1.f - wx0;
        const float v00 = xb[(size_t)(iy0 * WI + ix0) * CIN];
        const float v01 = xb[(size_t)(iy0 * WI + ix1) * CIN];
        const float v10 = xb[(size_t)(iy1 * WI + ix0) * CIN];
        const float v11 = xb[(size_t)(iy1 * WI + ix1) * CIN];
        dst[(size_t)c * CIN] = to_tf32(
            (wy0 * (wx0 * v00 + wx1 * v01) + wy1 * (wx0 * v10 + wx1 * v11)) * s);
    }
}

// ---------------- kernel 5: mma.sync tf32 conv + fused epilogue ------------
// CTA tile: M=256 (cout) x N=128 (pixels) x K-chunk 32; 144 chunks.
// 8 warps 4x2, warp tile 64x64. 3-stage cp.async pipeline.
// Smem row stride 40 floats: conflict-free for both cp.async STS.128 and
// float2 fragment gathers (LDS.64 phases: (8g+2tg) mod 32 distinct per phase).
#define ASTRIDE 40
#define A_ELEMS (256 * ASTRIDE)          // 10240 floats
#define B_ELEMS (128 * ASTRIDE)          // 5120 floats
#define STAGE_ELEMS (A_ELEMS + B_ELEMS)  // 15360
#define A_BYTES (A_ELEMS * 4)
#define STAGE_BYTES (STAGE_ELEMS * 4)    // 61440
#define CONV_SMEM (3 * STAGE_BYTES)      // 184320
#define NCHUNK 144

__global__ __launch_bounds__(256)
void conv_mma_kernel(const float* __restrict__ noise,
                     const float* __restrict__ nw_p,
                     float* __restrict__ out)
{
    extern __shared__ float sm[];
    const uint32_t sbase = smem_u32(sm);

    const int t = threadIdx.x;
    const int wid = t >> 5, lane = t & 31;
    const int g = lane >> 2, tg = lane & 3;
    const int wm = wid >> 1, wn = wid & 1;   // 4 x 2 warps

    const int cout0 = blockIdx.x * 256;
    const int py2   = blockIdx.y * 2;
    const int b     = blockIdx.z;

    const float* xmb = g_xm + (size_t)b * PADW * PADW * CIN;
    const int f4i = t & 7;     // 16B segment within 32-float k-chunk
    const int row0 = t >> 3;   // 0..31

    auto stage = [&](int it, int s) {
        const int tap = it >> 4;
        const int ci0 = (it & 15) << 5;
        const int ky = tap / 3, kx = tap - 3 * ky;
        const uint32_t abase = sbase + s * STAGE_BYTES;
        const float* wsrc = g_wt + (size_t)cout0 * KTOT + tap * CIN + ci0 + f4i * 4;
#pragma unroll
        for (int j = 0; j < 8; ++j) {
            const int row = row0 + 32 * j;
            cpasync16(abase + (uint32_t)(row * ASTRIDE + f4i * 4) * 4,
                      wsrc + (size_t)row * KTOT);
        }
        const uint32_t bbase = abase + A_BYTES;
#pragma unroll
        for (int j = 0; j < 4; ++j) {
            const int n = row0 + 32 * j;
            const int r = py2 + (n >> 6) + ky;
            const int c = (n & 63) + kx;
            cpasync16(bbase + (uint32_t)(n * ASTRIDE + f4i * 4) * 4,
                      xmb + ((size_t)r * PADW + c) * CIN + ci0 + f4i * 4);
        }
        cp_commit();
    };

    float acc[4][8][4];
#pragma unroll
    for (int mt = 0; mt < 4; ++mt)
#pragma unroll
        for (int nt = 0; nt < 8; ++nt)
#pragma unroll
            for (int q = 0; q < 4; ++q) acc[mt][nt][q] = 0.f;

    stage(0, 0);
    stage(1, 1);
    stage(2, 2);

    for (int it = 0; it < NCHUNK; ++it) {
        if (it < NCHUNK - 2)       cp_wait<2>();
        else if (it == NCHUNK - 2) cp_wait<1>();
        else                       cp_wait<0>();
        __syncthreads();

        const float* A = sm + (it % 3) * STAGE_ELEMS;
        const float* B = A + A_ELEMS;

#pragma unroll
        for (int k8 = 0; k8 < 4; ++k8) {
            const int kp = k8 * 8 + 2 * tg;   // paired (k, k+4)
            uint32_t a[4][4];
#pragma unroll
            for (int mt = 0; mt < 4; ++mt) {
                const int mb = wm * 64 + mt * 16;
                const float2 lo = *(const float2*)&A[(mb + g) * ASTRIDE + kp];
                const float2 hi = *(const float2*)&A[(mb + g + 8) * ASTRIDE + kp];
                a[mt][0] = __float_as_uint(lo.x);
                a[mt][1] = __float_as_uint(hi.x);
                a[mt][2] = __float_as_uint(lo.y);
                a[mt][3] = __float_as_uint(hi.y);
            }
#pragma unroll
            for (int nt = 0; nt < 8; ++nt) {
                const int nb = wn * 64 + nt * 8;
                const float2 bb = *(const float2*)&B[(nb + g) * ASTRIDE + kp];
                const uint32_t b0 = __float_as_uint(bb.x);
                const uint32_t b1 = __float_as_uint(bb.y);
#pragma unroll
                for (int mt = 0; mt < 4; ++mt)
                    mma_tf32(acc[mt][nt], a[mt], b0, b1);
            }
        }

        __syncthreads();
        if (it + 3 < NCHUNK) stage(it + 3, it % 3);
    }

    // fused epilogue: demod, noise, leaky relu, gain
    const float nwv = nw_p[0];
#pragma unroll
    for (int mt = 0; mt < 4; ++mt) {
        const int m0 = cout0 + wm * 64 + mt * 16 + g;
        const float dm0 = g_demod[b * COUT + m0];
        const float dm1 = g_demod[b * COUT + m0 + 8];
#pragma unroll
        for (int nt = 0; nt < 8; ++nt) {
            const int n = wn * 64 + nt * 8 + tg * 2;
            const int row = py2 + (n >> 6);
            const int col = n & 63;
            const float* nz = noise + ((size_t)b * HO + row) * WO + col;
            const float n0 = nwv * nz[0], n1 = nwv * nz[1];
            float* o0 = out + (((size_t)(b * COUT + m0)) * HO + row) * WO + col;
            float* o1 = o0 + (size_t)8 * HO * WO;
            float v;
            float2 r0, r1;
            v = acc[mt][nt][0] * dm0 + n0; r0.x = ((v >= 0.f) ? v : NEG_SLOPE * v) * ACT_GAIN;
            v = acc[mt][nt][1] * dm0 + n1; r0.y = ((v >= 0.f) ? v : NEG_SLOPE * v) * ACT_GAIN;
            v = acc[mt][nt][2] * dm1 + n0; r1.x = ((v >= 0.f) ? v : NEG_SLOPE * v) * ACT_GAIN;
            v = acc[mt][nt][3] * dm1 + n1; r1.y = ((v >= 0.f) ? v : NEG_SLOPE * v) * ACT_GAIN;
            *(float2*)o0 = r0;
            *(float2*)o1 = r1;
        }
    }
}

// ---------------- launch ----------------
extern "C" void kernel_launch(void* const* d_in, const int* in_sizes, int n_in,
                              void* d_out, int out_size)
{
    const float* x      = (const float*)d_in[0];
    const float* w      = (const float*)d_in[1];
    const float* noise  = (const float*)d_in[2];
    const float* lin_w  = (const float*)d_in[3];
    const float* lin_b  = (const float*)d_in[4];
    const float* conv_w = (const float*)d_in[5];
    const float* nw     = (const float*)d_in[6];
    float* out = (float*)d_out;

    cudaFuncSetAttribute(conv_mma_kernel,
                         cudaFuncAttributeMaxDynamicSharedMemorySize, CONV_SMEM);

    style_kernel<<<BB, SDIM>>>(w, lin_w, lin_b);
    wprep_kernel<<<COUT, CIN>>>(conv_w);
    demod_kernel<<<BB, COUT>>>();
    transpose_kernel<<<dim3(32, 16, 16), dim3(32, 8)>>>(x);
    upmod_cl_kernel<<<dim3(PADW, BB), CIN>>>();

    dim3 grid(COUT / 256, (HO * WO) / 128, BB);
    conv_mma_kernel<<<grid, 256, CONV_SMEM>>>(noise, nw, out);
}

// round 10
// speedup vs baseline: 1.7158x; 1.7158x over previous
#include <cuda_runtime.h>
#include <cuda_fp16.h>
#include <cstdint>

// ---------------- problem constants ----------------
#define BB    16
#define CIN   512
#define COUT  512
#define SDIM  512
#define HI    32
#define WI    32
#define HO    64
#define WO    64
#define PADW  66
#define KTOT  (9 * CIN)          // 4608

#define LIN_SCALE  0.04419417382415922f
#define CONV_SCALE 0.014731391274719742f
#define ACT_GAIN   1.4142135623730951f
#define NEG_SLOPE  0.2f
#define EPS_DEMOD  1e-8f

// ---------------- device scratch ----------------
__device__ float g_s[BB * CIN];
__device__ float g_demod[BB * COUT];
__device__ __align__(16) __half g_wt[(size_t)COUT * KTOT];            // fp16, word-pair-permuted
__device__ float g_wsq[COUT * CIN];
__device__ float g_xt[(size_t)BB * HI * WI * CIN];                    // channel-last input (fp32)
__device__ __align__(16) __half g_xm[(size_t)BB * PADW * PADW * CIN]; // fp16, permuted, padded upsample

// Word-pair permutation within each 16-half group: word w (0..7, w=k>>1)
// stored at position 2*(w&3) + (w>>2), so words (w, w+4) are adjacent.
// One LDS.64 then yields both k-halves of an m16n8k16 fragment (a0+a2 / b0+b1).
__device__ __forceinline__ int hperm(int i) {
    const int k = i & 15;
    const int w = k >> 1;
    const int p = ((w & 3) << 1) | (w >> 2);
    return (i & ~15) | (p << 1) | (k & 1);
}

// ---------------- helpers ----------------
__device__ __forceinline__ uint32_t smem_u32(const void* p) {
    uint32_t a;
    asm("{ .reg .u64 t; cvta.to.shared.u64 t, %1; cvt.u32.u64 %0, t; }"
        : "=r"(a) : "l"(p));
    return a;
}
__device__ __forceinline__ void cpasync16(uint32_t dst, const void* src) {
    asm volatile("cp.async.cg.shared.global [%0], [%1], 16;"
                 :: "r"(dst), "l"(src) : "memory");
}
__device__ __forceinline__ void cp_commit() {
    asm volatile("cp.async.commit_group;" ::: "memory");
}
template<int N> __device__ __forceinline__ void cp_wait() {
    asm volatile("cp.async.wait_group %0;" :: "n"(N) : "memory");
}
__device__ __forceinline__ void mma_f16(float* c, uint32_t a0, uint32_t a1,
                                        uint32_t a2, uint32_t a3,
                                        uint32_t b0, uint32_t b1) {
    asm volatile(
        "mma.sync.aligned.m16n8k16.row.col.f32.f16.f16.f32 "
        "{%0,%1,%2,%3}, {%4,%5,%6,%7}, {%8,%9}, {%0,%1,%2,%3};"
        : "+f"(c[0]), "+f"(c[1]), "+f"(c[2]), "+f"(c[3])
        : "r"(a0), "r"(a1), "r"(a2), "r"(a3), "r"(b0), "r"(b1));
}

// ---------------- kernel 1: style ----------------
__global__ void style_kernel(const float* __restrict__ w,
                             const float* __restrict__ lin_w,
                             const float* __restrict__ lin_b)
{
    const int b = blockIdx.x, i = threadIdx.x;
    __shared__ float ws[SDIM];
    ws[i] = w[b * SDIM + i];
    __syncthreads();
    const float* lw = lin_w + (size_t)i * SDIM;
    float acc = 0.f;
#pragma unroll 8
    for (int j = 0; j < SDIM; ++j) acc = fmaf(ws[j], lw[j], acc);
    g_s[b * CIN + i] = acc * LIN_SCALE + lin_b[i];
}

// ---------------- kernel 2: weight K-major (fp16, permuted) + sumsq --------
__global__ void wprep_kernel(const float* __restrict__ conv_w)
{
    const int o = blockIdx.x, i = threadIdx.x;
    const float* wp = conv_w + ((size_t)o * CIN + i) * 9;
    const int ip = hperm(i);
    float q = 0.f;
#pragma unroll
    for (int kk = 0; kk < 9; ++kk) {
        const float v = wp[kk] * CONV_SCALE;
        g_wt[(size_t)o * KTOT + kk * CIN + ip] = __float2half(v);
        q = fmaf(v, v, q);   // exact fp32 for demod
    }
    g_wsq[o * CIN + i] = q;
}

// ---------------- kernel 3: demod ----------------
__global__ void demod_kernel()
{
    const int b = blockIdx.x, o = threadIdx.x;
    __shared__ float s2[CIN];
    const float sv = g_s[b * CIN + o];
    s2[o] = sv * sv;
    __syncthreads();
    const float* wq = g_wsq + (size_t)o * CIN;
    float acc = 0.f;
#pragma unroll 8
    for (int i = 0; i < CIN; ++i) acc = fmaf(wq[i], s2[i], acc);
    g_demod[b * COUT + o] = rsqrtf(acc + EPS_DEMOD);
}

// ---------------- kernel 4a: transpose x to channel-last ----------------
__global__ void transpose_kernel(const float* __restrict__ x)
{
    __shared__ float tile[32][33];
    const int b = blockIdx.z, p0 = blockIdx.x * 32, c0 = blockIdx.y * 32;
    const int tx = threadIdx.x, ty = threadIdx.y;     // (32, 8)
    for (int i = ty; i < 32; i += 8)
        tile[i][tx] = x[((size_t)(b * CIN) + c0 + i) * (HI * WI) + p0 + tx];
    __syncthreads();
    for (int i = ty; i < 32; i += 8)
        g_xt[((size_t)(b * HI * WI) + p0 + i) * CIN + c0 + tx] = tile[tx][i];
}

// ------ kernel 4b: upsample*style, channel-last, zero halo, fp16, permuted -
__global__ void upmod_cl_kernel()
{
    const int r = blockIdx.x;         // 0..65
    const int b = blockIdx.y;
    const int ci = threadIdx.x;       // 512
    const int cip = hperm(ci);
    __half* dst = g_xm + ((size_t)(b * PADW + r) * PADW) * CIN + cip;
    const __half hz = __float2half(0.f);
    if (r == 0 || r == PADW - 1) {
        for (int c = 0; c < PADW; ++c) dst[(size_t)c * CIN] = hz;
        return;
    }
    const int oy = r - 1, my = oy >> 1;
    int iy0, iy1; float wy0;
    if (oy & 1) { iy0 = my; iy1 = min(my + 1, HI - 1); wy0 = 0.75f; }
    else        { iy0 = max(my - 1, 0); iy1 = my;      wy0 = 0.25f; }
    const float wy1 = 1.f - wy0;
    const float s = g_s[b * CIN + ci];
    const float* xb = g_xt + (size_t)b * HI * WI * CIN + ci;
    dst[0] = hz;
    dst[(size_t)(PADW - 1) * CIN] = hz;
    for (int c = 1; c < PADW - 1; ++c) {
        const int ox = c - 1, mx = ox >> 1;
        int ix0, ix1; float wx0;
        if (ox & 1) { ix0 = mx; ix1 = min(mx + 1, WI - 1); wx0 = 0.75f; }
        else        { ix0 = max(mx - 1, 0); ix1 = mx;      wx0 = 0.25f; }
        const float wx1 = 1.f - wx0;
        const float v00 = xb[(size_t)(iy0 * WI + ix0) * CIN];
        const float v01 = xb[(size_t)(iy0 * WI + ix1) * CIN];
        const float v10 = xb[(size_t)(iy1 * WI + ix0) * CIN];
        const float v11 = xb[(size_t)(iy1 * WI + ix1) * CIN];
        dst[(size_t)c * CIN] = __float2half(
            (wy0 * (wx0 * v00 + wx1 * v01) + wy1 * (wx0 * v10 + wx1 * v11)) * s);
    }
}

// ---------------- kernel 5: fp16 mma.sync conv + fused epilogue ------------
// CTA tile: M=256 (cout) x N=128 (pixels) x K-chunk 64 halfs; 72 chunks.
// 8 warps 4x2, warp tile 64x64, m16n8k16. 3-stage cp.async pipeline.
// Smem row stride 80 halfs (= 40 words, 40 mod 32 = 8): conflict-free for
// both cp.async 16B stores and LDS.64 fragment gathers ((8g+2tg) mod 32).
#define RS 80                              // halfs per smem row
#define A_HALFS (256 * RS)                 // 20480
#define B_HALFS (128 * RS)                 // 10240
#define STAGE_HALFS (A_HALFS + B_HALFS)    // 30720
#define A_BYTES (A_HALFS * 2)
#define STAGE_BYTES (STAGE_HALFS * 2)      // 61440
#define CONV_SMEM (3 * STAGE_BYTES)        // 184320
#define NCHUNK 72

__global__ __launch_bounds__(256)
void conv_mma_kernel(const float* __restrict__ noise,
                     const float* __restrict__ nw_p,
                     float* __restrict__ out)
{
    extern __shared__ __half sm[];
    const uint32_t sbase = smem_u32(sm);

    const int t = threadIdx.x;
    const int wid = t >> 5, lane = t & 31;
    const int g = lane >> 2, tg = lane & 3;
    const int wm = wid >> 1, wn = wid & 1;   // 4 x 2 warps

    const int cout0 = blockIdx.x * 256;
    const int py2   = blockIdx.y * 2;
    const int b     = blockIdx.z;

    const __half* xmb = g_xm + (size_t)b * PADW * PADW * CIN;
    const int f4i = t & 7;     // 16B (8-half) segment within 64-half k-chunk
    const int row0 = t >> 3;   // 0..31

    auto stage = [&](int it, int s) {
        const int tap = it >> 3;             // 8 chunks of 64 per tap
        const int ci0 = (it & 7) << 6;
        const int ky = tap / 3, kx = tap - 3 * ky;
        const uint32_t abase = sbase + s * STAGE_BYTES;
        const __half* wsrc = g_wt + (size_t)cout0 * KTOT + tap * CIN + ci0 + f4i * 8;
#pragma unroll
        for (int j = 0; j < 8; ++j) {
            const int row = row0 + 32 * j;
            cpasync16(abase + (uint32_t)(row * RS + f4i * 8) * 2,
                      wsrc + (size_t)row * KTOT);
        }
        const uint32_t bbase = abase + A_BYTES;
#pragma unroll
        for (int j = 0; j < 4; ++j) {
            const int n = row0 + 32 * j;
            const int r = py2 + (n >> 6) + ky;
            const int c = (n & 63) + kx;
            cpasync16(bbase + (uint32_t)(n * RS + f4i * 8) * 2,
                      xmb + ((size_t)r * PADW + c) * CIN + ci0 + f4i * 8);
        }
        cp_commit();
    };

    float acc[4][8][4];
#pragma unroll
    for (int mt = 0; mt < 4; ++mt)
#pragma unroll
        for (int nt = 0; nt < 8; ++nt)
#pragma unroll
            for (int q = 0; q < 4; ++q) acc[mt][nt][q] = 0.f;

    stage(0, 0);
    stage(1, 1);
    stage(2, 2);

    for (int it = 0; it < NCHUNK; ++it) {
        if (it < NCHUNK - 2)       cp_wait<2>();
        else if (it == NCHUNK - 2) cp_wait<1>();
        else                       cp_wait<0>();
        __syncthreads();

        const __half* A = sm + (it % 3) * STAGE_HALFS;
        const __half* B = A + A_HALFS;

#pragma unroll
        for (int ks = 0; ks < 4; ++ks) {
            const int off = ks * 16 + 4 * tg;   // permuted: word pair (tg, tg+4)
            uint2 afr[4][2];                    // [mt][row g / row g+8] = (a0,a2)/(a1,a3)
#pragma unroll
            for (int mt = 0; mt < 4; ++mt) {
                const int mb = wm * 64 + mt * 16;
                afr[mt][0] = *(const uint2*)&A[(mb + g) * RS + off];
                afr[mt][1] = *(const uint2*)&A[(mb + g + 8) * RS + off];
            }
#pragma unroll
            for (int nt = 0; nt < 8; ++nt) {
                const int nb = wn * 64 + nt * 8;
                const uint2 bfr = *(const uint2*)&B[(nb + g) * RS + off];  // (b0,b1)
#pragma unroll
                for (int mt = 0; mt < 4; ++mt)
                    mma_f16(acc[mt][nt],
                            afr[mt][0].x, afr[mt][1].x,
                            afr[mt][0].y, afr[mt][1].y,
                            bfr.x, bfr.y);
            }
        }

        __syncthreads();
        if (it + 3 < NCHUNK) stage(it + 3, it % 3);
    }

    // fused epilogue: demod, noise, leaky relu, gain
    const float nwv = nw_p[0];
#pragma unroll
    for (int mt = 0; mt < 4; ++mt) {
        const int m0 = cout0 + wm * 64 + mt * 16 + g;
        const float dm0 = g_demod[b * COUT + m0];
        const float dm1 = g_demod[b * COUT + m0 + 8];
#pragma unroll
        for (int nt = 0; nt < 8; ++nt) {
            const int n = wn * 64 + nt * 8 + tg * 2;
            const int row = py2 + (n >> 6);
            const int col = n & 63;
            const float* nz = noise + ((size_t)b * HO + row) * WO + col;
            const float n0 = nwv * nz[0], n1 = nwv * nz[1];
            float* o0 = out + (((size_t)(b * COUT + m0)) * HO + row) * WO + col;
            float* o1 = o0 + (size_t)8 * HO * WO;
            float v;
            float2 r0, r1;
            v = acc[mt][nt][0] * dm0 + n0; r0.x = ((v >= 0.f) ? v : NEG_SLOPE * v) * ACT_GAIN;
            v = acc[mt][nt][1] * dm0 + n1; r0.y = ((v >= 0.f) ? v : NEG_SLOPE * v) * ACT_GAIN;
            v = acc[mt][nt][2] * dm1 + n0; r1.x = ((v >= 0.f) ? v : NEG_SLOPE * v) * ACT_GAIN;
            v = acc[mt][nt][3] * dm1 + n1; r1.y = ((v >= 0.f) ? v : NEG_SLOPE * v) * ACT_GAIN;
            *(float2*)o0 = r0;
            *(float2*)o1 = r1;
        }
    }
}

// ---------------- launch ----------------
extern "C" void kernel_launch(void* const* d_in, const int* in_sizes, int n_in,
                              void* d_out, int out_size)
{
    const float* x      = (const float*)d_in[0];
    const float* w      = (const float*)d_in[1];
    const float* noise  = (const float*)d_in[2];
    const float* lin_w  = (const float*)d_in[3];
    const float* lin_b  = (const float*)d_in[4];
    const float* conv_w = (const float*)d_in[5];
    const float* nw     = (const float*)d_in[6];
    float* out = (float*)d_out;

    cudaFuncSetAttribute(conv_mma_kernel,
                         cudaFuncAttributeMaxDynamicSharedMemorySize, CONV_SMEM);

    style_kernel<<<BB, SDIM>>>(w, lin_w, lin_b);
    wprep_kernel<<<COUT, CIN>>>(conv_w);
    demod_kernel<<<BB, COUT>>>();
    transpose_kernel<<<dim3(32, 16, 16), dim3(32, 8)>>>(x);
    upmod_cl_kernel<<<dim3(PADW, BB), CIN>>>();

    dim3 grid(COUT / 256, (HO * WO) / 128, BB);
    conv_mma_kernel<<<grid, 256, CONV_SMEM>>>(noise, nw, out);
}

// round 11
// speedup vs baseline: 1.9104x; 1.1134x over previous
#include <cuda_runtime.h>
#include <cuda_fp16.h>
#include <cstdint>

// ---------------- problem constants ----------------
#define BB    16
#define CIN   512
#define COUT  512
#define SDIM  512
#define HI    32
#define WI    32
#define HO    64
#define WO    64
#define PADW  66
#define KTOT  (9 * CIN)          // 4608

#define LIN_SCALE  0.04419417382415922f
#define CONV_SCALE 0.014731391274719742f
#define ACT_GAIN   1.4142135623730951f
#define NEG_SLOPE  0.2f
#define EPS_DEMOD  1e-8f

// ---------------- device scratch ----------------
__device__ float g_s[BB * CIN];
__device__ float g_demod[BB * COUT];
__device__ __align__(16) __half g_wt[(size_t)COUT * KTOT];            // fp16, word-pair-permuted
__device__ float g_wsq[COUT * CIN];
__device__ float g_xt[(size_t)BB * HI * WI * CIN];                    // channel-last input (fp32)
__device__ __align__(16) __half g_xm[(size_t)BB * PADW * PADW * CIN]; // fp16, permuted, padded upsample

// Word-pair permutation within each 16-half group: word w (0..7, w=k>>1)
// stored at position 2*(w&3) + (w>>2), so words (w, w+4) are adjacent.
// One LDS.64 then yields both k-halves of an m16n8k16 fragment (a0+a2 / b0+b1).
__device__ __forceinline__ int hperm(int i) {
    const int k = i & 15;
    const int w = k >> 1;
    const int p = ((w & 3) << 1) | (w >> 2);
    return (i & ~15) | (p << 1) | (k & 1);
}

// ---------------- helpers ----------------
__device__ __forceinline__ uint32_t smem_u32(const void* p) {
    uint32_t a;
    asm("{ .reg .u64 t; cvta.to.shared.u64 t, %1; cvt.u32.u64 %0, t; }"
        : "=r"(a) : "l"(p));
    return a;
}
__device__ __forceinline__ void cpasync16(uint32_t dst, const void* src) {
    asm volatile("cp.async.cg.shared.global [%0], [%1], 16;"
                 :: "r"(dst), "l"(src) : "memory");
}
__device__ __forceinline__ void cp_commit() {
    asm volatile("cp.async.commit_group;" ::: "memory");
}
template<int N> __device__ __forceinline__ void cp_wait() {
    asm volatile("cp.async.wait_group %0;" :: "n"(N) : "memory");
}
__device__ __forceinline__ void mma_f16(float* c, uint32_t a0, uint32_t a1,
                                        uint32_t a2, uint32_t a3,
                                        uint32_t b0, uint32_t b1) {
    asm volatile(
        "mma.sync.aligned.m16n8k16.row.col.f32.f16.f16.f32 "
        "{%0,%1,%2,%3}, {%4,%5,%6,%7}, {%8,%9}, {%0,%1,%2,%3};"
        : "+f"(c[0]), "+f"(c[1]), "+f"(c[2]), "+f"(c[3])
        : "r"(a0), "r"(a1), "r"(a2), "r"(a3), "r"(b0), "r"(b1));
}

// ---------------- kernel 1: style ----------------
__global__ void style_kernel(const float* __restrict__ w,
                             const float* __restrict__ lin_w,
                             const float* __restrict__ lin_b)
{
    const int b = blockIdx.x, i = threadIdx.x;
    __shared__ float ws[SDIM];
    ws[i] = w[b * SDIM + i];
    __syncthreads();
    const float* lw = lin_w + (size_t)i * SDIM;
    float acc = 0.f;
#pragma unroll 8
    for (int j = 0; j < SDIM; ++j) acc = fmaf(ws[j], lw[j], acc);
    g_s[b * CIN + i] = acc * LIN_SCALE + lin_b[i];
}

// ---------------- kernel 2: weight K-major (fp16, permuted) + sumsq --------
__global__ void wprep_kernel(const float* __restrict__ conv_w)
{
    const int o = blockIdx.x, i = threadIdx.x;
    const float* wp = conv_w + ((size_t)o * CIN + i) * 9;
    const int ip = hperm(i);
    float q = 0.f;
#pragma unroll
    for (int kk = 0; kk < 9; ++kk) {
        const float v = wp[kk] * CONV_SCALE;
        g_wt[(size_t)o * KTOT + kk * CIN + ip] = __float2half(v);
        q = fmaf(v, v, q);   // exact fp32 for demod
    }
    g_wsq[o * CIN + i] = q;
}

// ---------------- kernel 3: demod ----------------
__global__ void demod_kernel()
{
    const int b = blockIdx.x, o = threadIdx.x;
    __shared__ float s2[CIN];
    const float sv = g_s[b * CIN + o];
    s2[o] = sv * sv;
    __syncthreads();
    const float* wq = g_wsq + (size_t)o * CIN;
    float acc = 0.f;
#pragma unroll 8
    for (int i = 0; i < CIN; ++i) acc = fmaf(wq[i], s2[i], acc);
    g_demod[b * COUT + o] = rsqrtf(acc + EPS_DEMOD);
}

// ---------------- kernel 4a: transpose x to channel-last ----------------
__global__ void transpose_kernel(const float* __restrict__ x)
{
    __shared__ float tile[32][33];
    const int b = blockIdx.z, p0 = blockIdx.x * 32, c0 = blockIdx.y * 32;
    const int tx = threadIdx.x, ty = threadIdx.y;     // (32, 8)
    for (int i = ty; i < 32; i += 8)
        tile[i][tx] = x[((size_t)(b * CIN) + c0 + i) * (HI * WI) + p0 + tx];
    __syncthreads();
    for (int i = ty; i < 32; i += 8)
        g_xt[((size_t)(b * HI * WI) + p0 + i) * CIN + c0 + tx] = tile[tx][i];
}

// ------ kernel 4b: upsample*style, channel-last, zero halo, fp16, permuted -
__global__ void upmod_cl_kernel()
{
    const int r = blockIdx.x;         // 0..65
    const int b = blockIdx.y;
    const int ci = threadIdx.x;       // 512
    const int cip = hperm(ci);
    __half* dst = g_xm + ((size_t)(b * PADW + r) * PADW) * CIN + cip;
    const __half hz = __float2half(0.f);
    if (r == 0 || r == PADW - 1) {
        for (int c = 0; c < PADW; ++c) dst[(size_t)c * CIN] = hz;
        return;
    }
    const int oy = r - 1, my = oy >> 1;
    int iy0, iy1; float wy0;
    if (oy & 1) { iy0 = my; iy1 = min(my + 1, HI - 1); wy0 = 0.75f; }
    else        { iy0 = max(my - 1, 0); iy1 = my;      wy0 = 0.25f; }
    const float wy1 = 1.f - wy0;
    const float s = g_s[b * CIN + ci];
    const float* xb = g_xt + (size_t)b * HI * WI * CIN + ci;
    dst[0] = hz;
    dst[(size_t)(PADW - 1) * CIN] = hz;
    for (int c = 1; c < PADW - 1; ++c) {
        const int ox = c - 1, mx = ox >> 1;
        int ix0, ix1; float wx0;
        if (ox & 1) { ix0 = mx; ix1 = min(mx + 1, WI - 1); wx0 = 0.75f; }
        else        { ix0 = max(mx - 1, 0); ix1 = mx;      wx0 = 0.25f; }
        const float wx1 = 1.f - wx0;
        const float v00 = xb[(size_t)(iy0 * WI + ix0) * CIN];
        const float v01 = xb[(size_t)(iy0 * WI + ix1) * CIN];
        const float v10 = xb[(size_t)(iy1 * WI + ix0) * CIN];
        const float v11 = xb[(size_t)(iy1 * WI + ix1) * CIN];
        dst[(size_t)c * CIN] = __float2half(
            (wy0 * (wx0 * v00 + wx1 * v01) + wy1 * (wx0 * v10 + wx1 * v11)) * s);
    }
}

// ---------------- kernel 5: fp16 mma.sync conv + fused epilogue ------------
// CTA tile: M=128 (cout) x N=128 (pixels) x K-chunk 64 halfs; 72 chunks.
// 8 warps 2x4, warp tile 64x32, m16n8k16. 2-stage pipeline, ONE barrier per
// chunk, 2 CTAs/SM (smem 80KB/CTA) so CTAs mutually hide barrier/wait bubbles.
// Smem row stride 80 halfs: conflict-free for cp.async 16B stores and LDS.64
// fragment gathers.
#define RS 80                              // halfs per smem row
#define A_HALFS (128 * RS)                 // 10240
#define B_HALFS (128 * RS)                 // 10240
#define STAGE_HALFS (A_HALFS + B_HALFS)    // 20480
#define A_BYTES (A_HALFS * 2)
#define STAGE_BYTES (STAGE_HALFS * 2)      // 40960
#define CONV_SMEM (2 * STAGE_BYTES)        // 81920
#define NCHUNK 72

__global__ __launch_bounds__(256, 2)
void conv_mma_kernel(const float* __restrict__ noise,
                     const float* __restrict__ nw_p,
                     float* __restrict__ out)
{
    extern __shared__ __half sm[];
    const uint32_t sbase = smem_u32(sm);

    const int t = threadIdx.x;
    const int wid = t >> 5, lane = t & 31;
    const int g = lane >> 2, tg = lane & 3;
    const int wm = wid & 1, wn = wid >> 1;   // 2 x 4 warps, warp tile 64x32

    const int cout0 = blockIdx.x * 128;
    const int py2   = blockIdx.y * 2;
    const int b     = blockIdx.z;

    const __half* xmb = g_xm + (size_t)b * PADW * PADW * CIN;
    const int f4i = t & 7;     // 16B (8-half) segment within 64-half k-chunk
    const int row0 = t >> 3;   // 0..31

    auto stage = [&](int it, int s) {
        const int tap = it >> 3;             // 8 chunks of 64 per tap
        const int ci0 = (it & 7) << 6;
        const int ky = tap / 3, kx = tap - 3 * ky;
        const uint32_t abase = sbase + s * STAGE_BYTES;
        const __half* wsrc = g_wt + (size_t)cout0 * KTOT + tap * CIN + ci0 + f4i * 8;
#pragma unroll
        for (int j = 0; j < 4; ++j) {
            const int row = row0 + 32 * j;
            cpasync16(abase + (uint32_t)(row * RS + f4i * 8) * 2,
                      wsrc + (size_t)row * KTOT);
        }
        const uint32_t bbase = abase + A_BYTES;
#pragma unroll
        for (int j = 0; j < 4; ++j) {
            const int n = row0 + 32 * j;
            const int r = py2 + (n >> 6) + ky;
            const int c = (n & 63) + kx;
            cpasync16(bbase + (uint32_t)(n * RS + f4i * 8) * 2,
                      xmb + ((size_t)r * PADW + c) * CIN + ci0 + f4i * 8);
        }
        cp_commit();
    };

    float acc[4][4][4];
#pragma unroll
    for (int mt = 0; mt < 4; ++mt)
#pragma unroll
        for (int nt = 0; nt < 4; ++nt)
#pragma unroll
            for (int q = 0; q < 4; ++q) acc[mt][nt][q] = 0.f;

    stage(0, 0);

    for (int it = 0; it < NCHUNK; ++it) {
        cp_wait<0>();            // stage(it) fully arrived
        __syncthreads();         // all warps past compute(it-1); slot (it+1)&1 reusable
        if (it + 1 < NCHUNK) stage(it + 1, (it + 1) & 1);

        const __half* A = sm + (it & 1) * STAGE_HALFS;
        const __half* B = A + A_HALFS;

#pragma unroll
        for (int ks = 0; ks < 4; ++ks) {
            const int off = ks * 16 + 4 * tg;   // permuted: word pair (tg, tg+4)
            uint2 afr[4][2];                    // [mt][row g / row g+8] = (a0,a2)/(a1,a3)
#pragma unroll
            for (int mt = 0; mt < 4; ++mt) {
                const int mb = wm * 64 + mt * 16;
                afr[mt][0] = *(const uint2*)&A[(mb + g) * RS + off];
                afr[mt][1] = *(const uint2*)&A[(mb + g + 8) * RS + off];
            }
#pragma unroll
            for (int nt = 0; nt < 4; ++nt) {
                const int nb = wn * 32 + nt * 8;
                const uint2 bfr = *(const uint2*)&B[(nb + g) * RS + off];  // (b0,b1)
#pragma unroll
                for (int mt = 0; mt < 4; ++mt)
                    mma_f16(acc[mt][nt],
                            afr[mt][0].x, afr[mt][1].x,
                            afr[mt][0].y, afr[mt][1].y,
                            bfr.x, bfr.y);
            }
        }
    }

    // fused epilogue: demod, noise, leaky relu, gain
    const float nwv = nw_p[0];
#pragma unroll
    for (int mt = 0; mt < 4; ++mt) {
        const int m0 = cout0 + wm * 64 + mt * 16 + g;
        const float dm0 = g_demod[b * COUT + m0];
        const float dm1 = g_demod[b * COUT + m0 + 8];
#pragma unroll
        for (int nt = 0; nt < 4; ++nt) {
            const int n = wn * 32 + nt * 8 + tg * 2;
            const int row = py2 + (n >> 6);
            const int col = n & 63;
            const float* nz = noise + ((size_t)b * HO + row) * WO + col;
            const float n0 = nwv * nz[0], n1 = nwv * nz[1];
            float* o0 = out + (((size_t)(b * COUT + m0)) * HO + row) * WO + col;
            float* o1 = o0 + (size_t)8 * HO * WO;
            float v;
            float2 r0, r1;
            v = acc[mt][nt][0] * dm0 + n0; r0.x = ((v >= 0.f) ? v : NEG_SLOPE * v) * ACT_GAIN;
            v = acc[mt][nt][1] * dm0 + n1; r0.y = ((v >= 0.f) ? v : NEG_SLOPE * v) * ACT_GAIN;
            v = acc[mt][nt][2] * dm1 + n0; r1.x = ((v >= 0.f) ? v : NEG_SLOPE * v) * ACT_GAIN;
            v = acc[mt][nt][3] * dm1 + n1; r1.y = ((v >= 0.f) ? v : NEG_SLOPE * v) * ACT_GAIN;
            *(float2*)o0 = r0;
            *(float2*)o1 = r1;
        }
    }
}

// ---------------- launch ----------------
extern "C" void kernel_launch(void* const* d_in, const int* in_sizes, int n_in,
                              void* d_out, int out_size)
{
    const float* x      = (const float*)d_in[0];
    const float* w      = (const float*)d_in[1];
    const float* noise  = (const float*)d_in[2];
    const float* lin_w  = (const float*)d_in[3];
    const float* lin_b  = (const float*)d_in[4];
    const float* conv_w = (const float*)d_in[5];
    const float* nw     = (const float*)d_in[6];
    float* out = (float*)d_out;

    cudaFuncSetAttribute(conv_mma_kernel,
                         cudaFuncAttributeMaxDynamicSharedMemorySize, CONV_SMEM);

    style_kernel<<<BB, SDIM>>>(w, lin_w, lin_b);
    wprep_kernel<<<COUT, CIN>>>(conv_w);
    demod_kernel<<<BB, COUT>>>();
    transpose_kernel<<<dim3(32, 16, 16), dim3(32, 8)>>>(x);
    upmod_cl_kernel<<<dim3(PADW, BB), CIN>>>();

    dim3 grid(COUT / 128, (HO * WO) / 128, BB);
    conv_mma_kernel<<<grid, 256, CONV_SMEM>>>(noise, nw, out);
}